// round 1
// baseline (speedup 1.0000x reference)
#include <cuda_runtime.h>
#include <cuda_bf16.h>

#define NN   100000
#define EE   1600000
#define CIN  256
#define COUT 128

// ---------------- scratch (static device globals; no allocation) ----------------
__device__ float g_feat[(size_t)NN * COUT];   // 51.2 MB, L2-resident working set
__device__ int   g_count[NN];
__device__ int   g_off[NN + 1];
__device__ int   g_cur[NN];
__device__ int   g_ecol[EE];
__device__ float g_eval[EE];

// ---------------- kernel 1: fused dropout + GEMM  feat = (emb*mask1) @ W^T + b_fc
// Block: 256 threads, tile 64 rows x 128 cols, K chunked by 16.
// Per-thread: 8 rows x 4 cols accumulators.
#define MT 64
#define KB 16

__global__ __launch_bounds__(256) void gemm_kernel(
    const float* __restrict__ emb, const float* __restrict__ mask1,
    const float* __restrict__ W, const float* __restrict__ b_fc)
{
    __shared__ float ws[KB][COUT];      // W chunk, transposed: ws[k][c]
    __shared__ float xs[KB][MT];        // x chunk, transposed: xs[k][row]

    const int tid  = threadIdx.x;
    const int row0 = blockIdx.x * MT;

    const int c4 = (tid & 31) * 4;      // col group (uniform row-group per warp)
    const int r8 = (tid >> 5) * 8;      // row group

    float acc[8][4];
#pragma unroll
    for (int i = 0; i < 8; i++)
#pragma unroll
        for (int j = 0; j < 4; j++) acc[i][j] = 0.f;

    for (int kb = 0; kb < CIN; kb += KB) {
        // --- stage x chunk: 64 rows x 16 k, with mask multiply ---
        {
            int row_l = tid >> 2;            // 0..63
            int kq    = (tid & 3) * 4;       // 0,4,8,12
            int grow  = row0 + row_l;
            float4 x4 = make_float4(0.f, 0.f, 0.f, 0.f);
            if (grow < NN) {
                const float4 e4 = *(const float4*)&emb  [(size_t)grow * CIN + kb + kq];
                const float4 m4 = *(const float4*)&mask1[(size_t)grow * CIN + kb + kq];
                x4.x = e4.x * m4.x; x4.y = e4.y * m4.y;
                x4.z = e4.z * m4.z; x4.w = e4.w * m4.w;
            }
            xs[kq + 0][row_l] = x4.x;
            xs[kq + 1][row_l] = x4.y;
            xs[kq + 2][row_l] = x4.z;
            xs[kq + 3][row_l] = x4.w;
        }
        // --- stage W chunk: 128 cols x 16 k ---
#pragma unroll
        for (int p = 0; p < 2; p++) {
            int c  = (tid >> 2) + p * 64;    // 0..127
            int kq = (tid & 3) * 4;
            const float4 w4 = *(const float4*)&W[(size_t)c * CIN + kb + kq];
            ws[kq + 0][c] = w4.x;
            ws[kq + 1][c] = w4.y;
            ws[kq + 2][c] = w4.z;
            ws[kq + 3][c] = w4.w;
        }
        __syncthreads();

        // --- compute ---
#pragma unroll
        for (int k = 0; k < KB; k++) {
            const float4 w  = *(const float4*)&ws[k][c4];
            const float4 xa = *(const float4*)&xs[k][r8];      // broadcast within warp
            const float4 xb = *(const float4*)&xs[k][r8 + 4];  // broadcast within warp
            const float xr[8] = {xa.x, xa.y, xa.z, xa.w, xb.x, xb.y, xb.z, xb.w};
            const float wr[4] = {w.x, w.y, w.z, w.w};
#pragma unroll
            for (int i = 0; i < 8; i++)
#pragma unroll
                for (int j = 0; j < 4; j++)
                    acc[i][j] = fmaf(xr[i], wr[j], acc[i][j]);
        }
        __syncthreads();
    }

    // --- epilogue: add b_fc, store feat ---
    const float4 bf = *(const float4*)&b_fc[c4];
#pragma unroll
    for (int i = 0; i < 8; i++) {
        int grow = row0 + r8 + i;
        if (grow < NN) {
            float4 o;
            o.x = acc[i][0] + bf.x;
            o.y = acc[i][1] + bf.y;
            o.z = acc[i][2] + bf.z;
            o.w = acc[i][3] + bf.w;
            *(float4*)&g_feat[(size_t)grow * COUT + c4] = o;
        }
    }
}

// ---------------- CSR construction ----------------
__global__ void zero_counts_kernel() {
    int i = blockIdx.x * blockDim.x + threadIdx.x;
    if (i < NN) g_count[i] = 0;
}

__global__ void hist_kernel(const int* __restrict__ rows) {
    int e = blockIdx.x * blockDim.x + threadIdx.x;
    if (e < EE) atomicAdd(&g_count[rows[e]], 1);
}

// single-block exclusive scan over g_count -> g_off (+ init g_cur)
__global__ __launch_bounds__(1024) void scan_kernel() {
    __shared__ int s[1024];
    const int T = 1024;
    const int CH = (NN + T - 1) / T;   // 98
    int t = threadIdx.x;
    int base = t * CH;

    int sum = 0;
    for (int i = 0; i < CH; i++) {
        int idx = base + i;
        if (idx < NN) sum += g_count[idx];
    }
    s[t] = sum;
    __syncthreads();
    for (int off = 1; off < T; off <<= 1) {
        int v = 0;
        if (t >= off) v = s[t - off];
        __syncthreads();
        if (t >= off) s[t] += v;
        __syncthreads();
    }
    int run = (t > 0) ? s[t - 1] : 0;   // exclusive prefix of this thread's chunk
    for (int i = 0; i < CH; i++) {
        int idx = base + i;
        if (idx < NN) {
            int c = g_count[idx];
            g_off[idx] = run;
            g_cur[idx] = run;
            run += c;
        }
    }
    if (t == T - 1) g_off[NN] = run;    // == EE
}

__global__ void scatter_kernel(const int* __restrict__ rows,
                               const int* __restrict__ cols,
                               const float* __restrict__ vals) {
    int e = blockIdx.x * blockDim.x + threadIdx.x;
    if (e < EE) {
        int r = rows[e];
        int p = atomicAdd(&g_cur[r], 1);
        g_ecol[p] = cols[e];
        g_eval[p] = vals[e];
    }
}

// ---------------- kernel: warp-per-row SpMM + fused epilogue ----------------
__global__ __launch_bounds__(256) void spmm_kernel(
    const float* __restrict__ bias, const float* __restrict__ mask2,
    const float* __restrict__ prelu_a, float* __restrict__ out)
{
    const int warp = blockIdx.x * 8 + (threadIdx.x >> 5);
    if (warp >= NN) return;
    const int lane = threadIdx.x & 31;

    const int start = g_off[warp];
    const int end   = g_off[warp + 1];

    const float4* __restrict__ featv = (const float4*)g_feat;  // 32 float4 per row

    float4 acc = make_float4(0.f, 0.f, 0.f, 0.f);

    for (int e0 = start; e0 < end; e0 += 32) {
        const int n = min(32, end - e0);
        int   c = 0;
        float v = 0.f;
        if (lane < n) {
            c = g_ecol[e0 + lane];
            v = g_eval[e0 + lane];
        }
#pragma unroll 4
        for (int j = 0; j < n; j++) {
            const int   cj = __shfl_sync(0xffffffffu, c, j);
            const float vj = __shfl_sync(0xffffffffu, v, j);
            const float4 f = featv[(size_t)cj * 32 + lane];
            acc.x = fmaf(vj, f.x, acc.x);
            acc.y = fmaf(vj, f.y, acc.y);
            acc.z = fmaf(vj, f.z, acc.z);
            acc.w = fmaf(vj, f.w, acc.w);
        }
    }

    // epilogue: +bias, *mask2, PReLU
    const float4 b = ((const float4*)bias)[lane];
    const float4 m = ((const float4*)mask2)[(size_t)warp * 32 + lane];
    const float  a = prelu_a[0];

    float4 o;
    o.x = (acc.x + b.x) * m.x;
    o.y = (acc.y + b.y) * m.y;
    o.z = (acc.z + b.z) * m.z;
    o.w = (acc.w + b.w) * m.w;
    o.x = o.x > 0.f ? o.x : a * o.x;
    o.y = o.y > 0.f ? o.y : a * o.y;
    o.z = o.z > 0.f ? o.z : a * o.z;
    o.w = o.w > 0.f ? o.w : a * o.w;

    ((float4*)out)[(size_t)warp * 32 + lane] = o;
}

// ---------------- launch ----------------
extern "C" void kernel_launch(void* const* d_in, const int* in_sizes, int n_in,
                              void* d_out, int out_size)
{
    const float* emb     = (const float*)d_in[0];
    const float* vals    = (const float*)d_in[1];
    const float* W       = (const float*)d_in[2];
    const float* b_fc    = (const float*)d_in[3];
    const float* bias    = (const float*)d_in[4];
    const float* prelu_a = (const float*)d_in[5];
    const float* mask1   = (const float*)d_in[6];
    const float* mask2   = (const float*)d_in[7];
    const int*   rows    = (const int*)d_in[8];
    const int*   cols    = (const int*)d_in[9];
    float*       out     = (float*)d_out;

    // GEMM: feat = (emb*mask1) @ W^T + b_fc
    gemm_kernel<<<(NN + MT - 1) / MT, 256>>>(emb, mask1, W, b_fc);

    // CSR build
    zero_counts_kernel<<<(NN + 255) / 256, 256>>>();
    hist_kernel<<<(EE + 255) / 256, 256>>>(rows);
    scan_kernel<<<1, 1024>>>();
    scatter_kernel<<<(EE + 255) / 256, 256>>>(rows, cols, vals);

    // SpMM + epilogue (warp per row, 8 warps per block)
    spmm_kernel<<<(NN + 7) / 8, 256>>>(bias, mask2, prelu_a, out);
}

// round 2
// speedup vs baseline: 1.5191x; 1.5191x over previous
#include <cuda_runtime.h>
#include <cuda_bf16.h>

#define NN   100000
#define EE   1600000
#define CIN  256
#define COUT 128

#define SCAN_B 1024
#define SCAN_NB ((NN + SCAN_B - 1) / SCAN_B)   // 98

// ---------------- scratch (static device globals; no allocation) ----------------
__device__ float g_feat[(size_t)NN * COUT];   // 51.2 MB, mostly L2-resident
__device__ int   g_count[NN];
__device__ int   g_off[NN + 1];
__device__ int   g_cur[NN];
__device__ int   g_bsum[SCAN_NB];
__device__ int   g_bpre[SCAN_NB];
__device__ int   g_ecol[EE];
__device__ float g_eval[EE];

// ---------------- f32x2 helpers (Blackwell packed dual-fp32) ----------------
typedef unsigned long long ull;

__device__ __forceinline__ ull pack2(float lo, float hi) {
    ull r;
    asm("mov.b64 %0, {%1, %2};" : "=l"(r) : "f"(lo), "f"(hi));
    return r;
}
__device__ __forceinline__ void unpack2(float& lo, float& hi, ull v) {
    asm("mov.b64 {%0, %1}, %2;" : "=f"(lo), "=f"(hi) : "l"(v));
}
__device__ __forceinline__ void ffma2(ull& d, ull a, ull b) {
    asm("fma.rn.f32x2 %0, %1, %2, %0;" : "+l"(d) : "l"(a), "l"(b));
}

// ---------------- kernel 1: fused dropout + GEMM  feat = (emb*mask1) @ W^T + b_fc
// Block: 256 threads, tile 64 rows x 128 cols, K chunked by 16.
// Per-thread: 8 rows x 4 cols accumulators, stored as 4 row-pair f32x2 x 4 cols.
#define MT 64
#define KB 16

__global__ __launch_bounds__(256) void gemm_kernel(
    const float* __restrict__ emb, const float* __restrict__ mask1,
    const float* __restrict__ W, const float* __restrict__ b_fc)
{
    __shared__ float ws[KB][COUT];      // W chunk, transposed: ws[k][c]
    __shared__ float xs[KB][MT];        // x chunk, transposed: xs[k][row]

    const int tid  = threadIdx.x;
    const int row0 = blockIdx.x * MT;

    const int c4 = (tid & 31) * 4;      // col group (varies per lane)
    const int r8 = (tid >> 5) * 8;      // row group (uniform per warp)

    // acc2[i][j]: rows (r8+2i, r8+2i+1) packed as f32x2, col c4+j
    ull acc2[4][4];
#pragma unroll
    for (int i = 0; i < 4; i++)
#pragma unroll
        for (int j = 0; j < 4; j++) acc2[i][j] = 0ull;

    for (int kb = 0; kb < CIN; kb += KB) {
        // --- stage x chunk: 64 rows x 16 k, with mask multiply ---
        {
            int row_l = tid >> 2;            // 0..63
            int kq    = (tid & 3) * 4;       // 0,4,8,12
            int grow  = row0 + row_l;
            float4 x4 = make_float4(0.f, 0.f, 0.f, 0.f);
            if (grow < NN) {
                const float4 e4 = *(const float4*)&emb  [(size_t)grow * CIN + kb + kq];
                const float4 m4 = *(const float4*)&mask1[(size_t)grow * CIN + kb + kq];
                x4.x = e4.x * m4.x; x4.y = e4.y * m4.y;
                x4.z = e4.z * m4.z; x4.w = e4.w * m4.w;
            }
            xs[kq + 0][row_l] = x4.x;
            xs[kq + 1][row_l] = x4.y;
            xs[kq + 2][row_l] = x4.z;
            xs[kq + 3][row_l] = x4.w;
        }
        // --- stage W chunk: 128 cols x 16 k ---
#pragma unroll
        for (int p = 0; p < 2; p++) {
            int c  = (tid >> 2) + p * 64;    // 0..127
            int kq = (tid & 3) * 4;
            const float4 w4 = *(const float4*)&W[(size_t)c * CIN + kb + kq];
            ws[kq + 0][c] = w4.x;
            ws[kq + 1][c] = w4.y;
            ws[kq + 2][c] = w4.z;
            ws[kq + 3][c] = w4.w;
        }
        __syncthreads();

        // --- compute (packed f32x2 FMA) ---
#pragma unroll
        for (int k = 0; k < KB; k++) {
            const float4 w = *(const float4*)&ws[k][c4];          // LDS.128
            const ull wp0 = pack2(w.x, w.x);
            const ull wp1 = pack2(w.y, w.y);
            const ull wp2 = pack2(w.z, w.z);
            const ull wp3 = pack2(w.w, w.w);
            // 8 row values as 4 natural f32x2 pairs straight from LDS.128 regs
            const ulonglong2 xa = *(const ulonglong2*)&xs[k][r8];     // rows r8..r8+3
            const ulonglong2 xb = *(const ulonglong2*)&xs[k][r8 + 4]; // rows r8+4..r8+7
            const ull xp[4] = {xa.x, xa.y, xb.x, xb.y};
#pragma unroll
            for (int i = 0; i < 4; i++) {
                ffma2(acc2[i][0], xp[i], wp0);
                ffma2(acc2[i][1], xp[i], wp1);
                ffma2(acc2[i][2], xp[i], wp2);
                ffma2(acc2[i][3], xp[i], wp3);
            }
        }
        __syncthreads();
    }

    // --- epilogue: add b_fc, store feat ---
    const float4 bf = *(const float4*)&b_fc[c4];
#pragma unroll
    for (int i = 0; i < 4; i++) {
        float lo0, hi0, lo1, hi1, lo2, hi2, lo3, hi3;
        unpack2(lo0, hi0, acc2[i][0]);
        unpack2(lo1, hi1, acc2[i][1]);
        unpack2(lo2, hi2, acc2[i][2]);
        unpack2(lo3, hi3, acc2[i][3]);
        int grow0 = row0 + r8 + 2 * i;
        if (grow0 < NN) {
            float4 o;
            o.x = lo0 + bf.x; o.y = lo1 + bf.y; o.z = lo2 + bf.z; o.w = lo3 + bf.w;
            *(float4*)&g_feat[(size_t)grow0 * COUT + c4] = o;
        }
        if (grow0 + 1 < NN) {
            float4 o;
            o.x = hi0 + bf.x; o.y = hi1 + bf.y; o.z = hi2 + bf.z; o.w = hi3 + bf.w;
            *(float4*)&g_feat[(size_t)(grow0 + 1) * COUT + c4] = o;
        }
    }
}

// ---------------- CSR construction ----------------
__global__ void zero_counts_kernel() {
    int i = blockIdx.x * blockDim.x + threadIdx.x;
    if (i < NN) g_count[i] = 0;
}

__global__ void hist_kernel(const int* __restrict__ rows) {
    int e = blockIdx.x * blockDim.x + threadIdx.x;
    if (e < EE) atomicAdd(&g_count[rows[e]], 1);
}

// Phase 1: per-block inclusive scan -> local exclusive prefix in g_off, block sums
__global__ __launch_bounds__(SCAN_B) void scan1_kernel() {
    __shared__ int s[SCAN_B];
    const int t = threadIdx.x;
    const int b = blockIdx.x;
    const int idx = b * SCAN_B + t;
    const int v = (idx < NN) ? g_count[idx] : 0;
    s[t] = v;
    __syncthreads();
#pragma unroll
    for (int off = 1; off < SCAN_B; off <<= 1) {
        int u = 0;
        if (t >= off) u = s[t - off];
        __syncthreads();
        if (t >= off) s[t] += u;
        __syncthreads();
    }
    if (idx < NN) g_off[idx] = s[t] - v;         // local exclusive prefix
    if (t == SCAN_B - 1) g_bsum[b] = s[t];       // block total
}

// Phase 2: single small block scans the 98 block sums (exclusive)
__global__ __launch_bounds__(128) void scan2_kernel() {
    __shared__ int s[128];
    const int t = threadIdx.x;
    const int v = (t < SCAN_NB) ? g_bsum[t] : 0;
    s[t] = v;
    __syncthreads();
#pragma unroll
    for (int off = 1; off < 128; off <<= 1) {
        int u = 0;
        if (t >= off) u = s[t - off];
        __syncthreads();
        if (t >= off) s[t] += u;
        __syncthreads();
    }
    if (t < SCAN_NB) g_bpre[t] = s[t] - v;       // exclusive block prefix
}

// Phase 3: add block prefixes, init cursors, set sentinel
__global__ __launch_bounds__(SCAN_B) void scan3_kernel() {
    const int b = blockIdx.x;
    const int idx = b * SCAN_B + threadIdx.x;
    if (idx < NN) {
        const int o = g_off[idx] + g_bpre[b];
        g_off[idx] = o;
        g_cur[idx] = o;
    }
    if (idx == 0) g_off[NN] = EE;
}

__global__ void scatter_kernel(const int* __restrict__ rows,
                               const int* __restrict__ cols,
                               const float* __restrict__ vals) {
    int e = blockIdx.x * blockDim.x + threadIdx.x;
    if (e < EE) {
        int r = rows[e];
        int p = atomicAdd(&g_cur[r], 1);
        g_ecol[p] = cols[e];
        g_eval[p] = vals[e];
    }
}

// ---------------- kernel: warp-per-row SpMM + fused epilogue ----------------
__global__ __launch_bounds__(256) void spmm_kernel(
    const float* __restrict__ bias, const float* __restrict__ mask2,
    const float* __restrict__ prelu_a, float* __restrict__ out)
{
    const int warp = blockIdx.x * 8 + (threadIdx.x >> 5);
    if (warp >= NN) return;
    const int lane = threadIdx.x & 31;

    const int start = g_off[warp];
    const int end   = g_off[warp + 1];

    const float4* __restrict__ featv = (const float4*)g_feat;  // 32 float4 per row

    float4 acc = make_float4(0.f, 0.f, 0.f, 0.f);

    for (int e0 = start; e0 < end; e0 += 32) {
        const int n = min(32, end - e0);
        int   c = 0;
        float v = 0.f;
        if (lane < n) {
            c = g_ecol[e0 + lane];
            v = g_eval[e0 + lane];
        }
#pragma unroll 4
        for (int j = 0; j < n; j++) {
            const int   cj = __shfl_sync(0xffffffffu, c, j);
            const float vj = __shfl_sync(0xffffffffu, v, j);
            const float4 f = featv[(size_t)cj * 32 + lane];
            acc.x = fmaf(vj, f.x, acc.x);
            acc.y = fmaf(vj, f.y, acc.y);
            acc.z = fmaf(vj, f.z, acc.z);
            acc.w = fmaf(vj, f.w, acc.w);
        }
    }

    // epilogue: +bias, *mask2, PReLU
    const float4 b = ((const float4*)bias)[lane];
    const float4 m = ((const float4*)mask2)[(size_t)warp * 32 + lane];
    const float  a = prelu_a[0];

    float4 o;
    o.x = (acc.x + b.x) * m.x;
    o.y = (acc.y + b.y) * m.y;
    o.z = (acc.z + b.z) * m.z;
    o.w = (acc.w + b.w) * m.w;
    o.x = o.x > 0.f ? o.x : a * o.x;
    o.y = o.y > 0.f ? o.y : a * o.y;
    o.z = o.z > 0.f ? o.z : a * o.z;
    o.w = o.w > 0.f ? o.w : a * o.w;

    ((float4*)out)[(size_t)warp * 32 + lane] = o;
}

// ---------------- launch ----------------
extern "C" void kernel_launch(void* const* d_in, const int* in_sizes, int n_in,
                              void* d_out, int out_size)
{
    const float* emb     = (const float*)d_in[0];
    const float* vals    = (const float*)d_in[1];
    const float* W       = (const float*)d_in[2];
    const float* b_fc    = (const float*)d_in[3];
    const float* bias    = (const float*)d_in[4];
    const float* prelu_a = (const float*)d_in[5];
    const float* mask1   = (const float*)d_in[6];
    const float* mask2   = (const float*)d_in[7];
    const int*   rows    = (const int*)d_in[8];
    const int*   cols    = (const int*)d_in[9];
    float*       out     = (float*)d_out;

    // GEMM: feat = (emb*mask1) @ W^T + b_fc
    gemm_kernel<<<(NN + MT - 1) / MT, 256>>>(emb, mask1, W, b_fc);

    // CSR build
    zero_counts_kernel<<<(NN + 255) / 256, 256>>>();
    hist_kernel<<<(EE + 255) / 256, 256>>>(rows);
    scan1_kernel<<<SCAN_NB, SCAN_B>>>();
    scan2_kernel<<<1, 128>>>();
    scan3_kernel<<<SCAN_NB, SCAN_B>>>();
    scatter_kernel<<<(EE + 255) / 256, 256>>>(rows, cols, vals);

    // SpMM + epilogue (warp per row, 8 warps per block)
    spmm_kernel<<<(NN + 7) / 8, 256>>>(bias, mask2, prelu_a, out);
}

// round 4
// speedup vs baseline: 2.0906x; 1.3762x over previous
#include <cuda_runtime.h>
#include <cstdint>

#define NN   100000
#define EE   1600000
#define CIN  256
#define COUT 128

#define SCAN_B 1024
#define SCAN_NB ((NN + SCAN_B - 1) / SCAN_B)   // 98

// ---------------- scratch (static device globals; no allocation) ----------------
__device__ float g_feat[(size_t)NN * COUT];   // 51.2 MB
__device__ int   g_count[NN];
__device__ int   g_off[NN + 1];
__device__ int   g_cur[NN];
__device__ int   g_bsum[SCAN_NB];
__device__ int   g_bpre[SCAN_NB];
__device__ int   g_ecol[EE];
__device__ float g_eval[EE];

// ---------------- helpers ----------------
__device__ __forceinline__ uint32_t f2tf32(float f) {
    uint32_t r;
    asm("cvt.rna.tf32.f32 %0, %1;" : "=r"(r) : "f"(f));
    return r;
}

__device__ __forceinline__ void mma_tf32(float* c, const uint32_t* a, uint32_t b0, uint32_t b1) {
    asm volatile(
        "mma.sync.aligned.m16n8k8.row.col.f32.tf32.tf32.f32 "
        "{%0,%1,%2,%3}, {%4,%5,%6,%7}, {%8,%9}, {%0,%1,%2,%3};"
        : "+f"(c[0]), "+f"(c[1]), "+f"(c[2]), "+f"(c[3])
        : "r"(a[0]), "r"(a[1]), "r"(a[2]), "r"(a[3]), "r"(b0), "r"(b1));
}

// ---------------- GEMM: feat = (emb*mask1) @ W^T + b_fc  (tf32 mma.sync) -------
// CTA: 256 threads (8 warps, 4x2), tile M=128 x N=128, K chunked by 32.
// Warp tile 32x64. m16n8k8 fragments loaded from padded tf32 smem.
#define KB 32
#define KPAD (KB + 4)

__global__ __launch_bounds__(256) void gemm_mma_kernel(
    const float* __restrict__ emb, const float* __restrict__ mask1,
    const float* __restrict__ W, const float* __restrict__ b_fc)
{
    __shared__ uint32_t as[128][KPAD];   // A tile (tf32 bits), rows x k
    __shared__ uint32_t bs[128][KPAD];   // B tile = W rows (output cols) x k

    const int tid   = threadIdx.x;
    const int wid   = tid >> 5;
    const int lane  = tid & 31;
    const int warpM = wid >> 1;          // 0..3
    const int warpN = wid & 1;           // 0..1
    const int grp   = lane >> 2;         // 0..7
    const int tig   = lane & 3;          // 0..3
    const int row0  = blockIdx.x * 128;

    float acc[2][8][4];
#pragma unroll
    for (int mt = 0; mt < 2; mt++)
#pragma unroll
        for (int nt = 0; nt < 8; nt++)
#pragma unroll
            for (int j = 0; j < 4; j++) acc[mt][nt][j] = 0.f;

    for (int kc = 0; kc < CIN; kc += KB) {
        // --- stage A: (emb*mask1) -> tf32, 128 rows x 32 k ---
#pragma unroll
        for (int i = 0; i < 4; i++) {
            const int idx = i * 256 + tid;       // float4 index, 0..1023
            const int row = idx >> 3;            // 0..127
            const int kq  = (idx & 7) * 4;       // 0..28
            const int grow = row0 + row;
            float4 e = make_float4(0.f, 0.f, 0.f, 0.f);
            if (grow < NN) {
                const float4 a4 = *(const float4*)&emb  [(size_t)grow * CIN + kc + kq];
                const float4 m4 = *(const float4*)&mask1[(size_t)grow * CIN + kc + kq];
                e.x = a4.x * m4.x; e.y = a4.y * m4.y;
                e.z = a4.z * m4.z; e.w = a4.w * m4.w;
            }
            uint4 t;
            t.x = f2tf32(e.x); t.y = f2tf32(e.y); t.z = f2tf32(e.z); t.w = f2tf32(e.w);
            *(uint4*)&as[row][kq] = t;
        }
        // --- stage B: W (COUT x CIN, K-major) -> tf32, 128 rows x 32 k ---
#pragma unroll
        for (int i = 0; i < 4; i++) {
            const int idx = i * 256 + tid;
            const int row = idx >> 3;            // output col
            const int kq  = (idx & 7) * 4;
            const float4 w4 = *(const float4*)&W[(size_t)row * CIN + kc + kq];
            uint4 t;
            t.x = f2tf32(w4.x); t.y = f2tf32(w4.y); t.z = f2tf32(w4.z); t.w = f2tf32(w4.w);
            *(uint4*)&bs[row][kq] = t;
        }
        __syncthreads();

        // --- compute: 4 k8-steps ---
#pragma unroll
        for (int ks = 0; ks < 4; ks++) {
            const int k0 = ks * 8;
            uint32_t afr[2][4];
#pragma unroll
            for (int mt = 0; mt < 2; mt++) {
                const int r = warpM * 32 + mt * 16 + grp;
                afr[mt][0] = as[r][k0 + tig];
                afr[mt][1] = as[r + 8][k0 + tig];
                afr[mt][2] = as[r][k0 + tig + 4];
                afr[mt][3] = as[r + 8][k0 + tig + 4];
            }
#pragma unroll
            for (int nt = 0; nt < 8; nt++) {
                const int c = warpN * 64 + nt * 8 + grp;
                const uint32_t b0 = bs[c][k0 + tig];
                const uint32_t b1 = bs[c][k0 + tig + 4];
                mma_tf32(acc[0][nt], afr[0], b0, b1);
                mma_tf32(acc[1][nt], afr[1], b0, b1);
            }
        }
        __syncthreads();
    }

    // --- epilogue: +b_fc, store feat ---
#pragma unroll
    for (int mt = 0; mt < 2; mt++) {
        const int r0 = row0 + warpM * 32 + mt * 16 + grp;
        const int r1 = r0 + 8;
#pragma unroll
        for (int nt = 0; nt < 8; nt++) {
            const int col = warpN * 64 + nt * 8 + 2 * tig;
            const float2 bf = *(const float2*)&b_fc[col];
            if (r0 < NN) {
                float2 o;
                o.x = acc[mt][nt][0] + bf.x;
                o.y = acc[mt][nt][1] + bf.y;
                *(float2*)&g_feat[(size_t)r0 * COUT + col] = o;
            }
            if (r1 < NN) {
                float2 o;
                o.x = acc[mt][nt][2] + bf.x;
                o.y = acc[mt][nt][3] + bf.y;
                *(float2*)&g_feat[(size_t)r1 * COUT + col] = o;
            }
        }
    }
}

// ---------------- CSR construction ----------------
__global__ void zero_counts_kernel() {
    int i = blockIdx.x * blockDim.x + threadIdx.x;
    if (i < NN) g_count[i] = 0;
}

__global__ void hist_kernel(const int* __restrict__ rows) {
    int e = blockIdx.x * blockDim.x + threadIdx.x;
    if (e < EE) atomicAdd(&g_count[rows[e]], 1);
}

__global__ __launch_bounds__(SCAN_B) void scan1_kernel() {
    __shared__ int s[SCAN_B];
    const int t = threadIdx.x;
    const int b = blockIdx.x;
    const int idx = b * SCAN_B + t;
    const int v = (idx < NN) ? g_count[idx] : 0;
    s[t] = v;
    __syncthreads();
#pragma unroll
    for (int off = 1; off < SCAN_B; off <<= 1) {
        int u = 0;
        if (t >= off) u = s[t - off];
        __syncthreads();
        if (t >= off) s[t] += u;
        __syncthreads();
    }
    if (idx < NN) g_off[idx] = s[t] - v;
    if (t == SCAN_B - 1) g_bsum[b] = s[t];
}

__global__ __launch_bounds__(128) void scan2_kernel() {
    __shared__ int s[128];
    const int t = threadIdx.x;
    const int v = (t < SCAN_NB) ? g_bsum[t] : 0;
    s[t] = v;
    __syncthreads();
#pragma unroll
    for (int off = 1; off < 128; off <<= 1) {
        int u = 0;
        if (t >= off) u = s[t - off];
        __syncthreads();
        if (t >= off) s[t] += u;
        __syncthreads();
    }
    if (t < SCAN_NB) g_bpre[t] = s[t] - v;
}

__global__ __launch_bounds__(SCAN_B) void scan3_kernel() {
    const int b = blockIdx.x;
    const int idx = b * SCAN_B + threadIdx.x;
    if (idx < NN) {
        const int o = g_off[idx] + g_bpre[b];
        g_off[idx] = o;
        g_cur[idx] = o;
    }
    if (idx == 0) g_off[NN] = EE;
}

__global__ void scatter_kernel(const int* __restrict__ rows,
                               const int* __restrict__ cols,
                               const float* __restrict__ vals) {
    int e = blockIdx.x * blockDim.x + threadIdx.x;
    if (e < EE) {
        int r = rows[e];
        int p = atomicAdd(&g_cur[r], 1);
        g_ecol[p] = cols[e];
        g_eval[p] = vals[e];
    }
}

// ---------------- warp-per-row SpMM + fused epilogue ----------------
__global__ __launch_bounds__(256) void spmm_kernel(
    const float* __restrict__ bias, const float* __restrict__ mask2,
    const float* __restrict__ prelu_a, float* __restrict__ out)
{
    const int warp = blockIdx.x * 8 + (threadIdx.x >> 5);
    if (warp >= NN) return;
    const int lane = threadIdx.x & 31;

    const int start = g_off[warp];
    const int end   = g_off[warp + 1];

    const float4* __restrict__ featv = (const float4*)g_feat;

    float4 acc = make_float4(0.f, 0.f, 0.f, 0.f);

    for (int e0 = start; e0 < end; e0 += 32) {
        const int n = min(32, end - e0);
        int   c = 0;
        float v = 0.f;
        if (lane < n) {
            c = g_ecol[e0 + lane];
            v = g_eval[e0 + lane];
        }
#pragma unroll 4
        for (int j = 0; j < n; j++) {
            const int   cj = __shfl_sync(0xffffffffu, c, j);
            const float vj = __shfl_sync(0xffffffffu, v, j);
            const float4 f = featv[(size_t)cj * 32 + lane];
            acc.x = fmaf(vj, f.x, acc.x);
            acc.y = fmaf(vj, f.y, acc.y);
            acc.z = fmaf(vj, f.z, acc.z);
            acc.w = fmaf(vj, f.w, acc.w);
        }
    }

    const float4 b = ((const float4*)bias)[lane];
    const float4 m = ((const float4*)mask2)[(size_t)warp * 32 + lane];
    const float  a = prelu_a[0];

    float4 o;
    o.x = (acc.x + b.x) * m.x;
    o.y = (acc.y + b.y) * m.y;
    o.z = (acc.z + b.z) * m.z;
    o.w = (acc.w + b.w) * m.w;
    o.x = o.x > 0.f ? o.x : a * o.x;
    o.y = o.y > 0.f ? o.y : a * o.y;
    o.z = o.z > 0.f ? o.z : a * o.z;
    o.w = o.w > 0.f ? o.w : a * o.w;

    ((float4*)out)[(size_t)warp * 32 + lane] = o;
}

// ---------------- launch ----------------
extern "C" void kernel_launch(void* const* d_in, const int* in_sizes, int n_in,
                              void* d_out, int out_size)
{
    const float* emb     = (const float*)d_in[0];
    const float* vals    = (const float*)d_in[1];
    const float* W       = (const float*)d_in[2];
    const float* b_fc    = (const float*)d_in[3];
    const float* bias    = (const float*)d_in[4];
    const float* prelu_a = (const float*)d_in[5];
    const float* mask1   = (const float*)d_in[6];
    const float* mask2   = (const float*)d_in[7];
    const int*   rows    = (const int*)d_in[8];
    const int*   cols    = (const int*)d_in[9];
    float*       out     = (float*)d_out;

    // GEMM via tf32 mma.sync: feat = (emb*mask1) @ W^T + b_fc
    gemm_mma_kernel<<<(NN + 127) / 128, 256>>>(emb, mask1, W, b_fc);

    // CSR build
    zero_counts_kernel<<<(NN + 255) / 256, 256>>>();
    hist_kernel<<<(EE + 255) / 256, 256>>>(rows);
    scan1_kernel<<<SCAN_NB, SCAN_B>>>();
    scan2_kernel<<<1, 128>>>();
    scan3_kernel<<<SCAN_NB, SCAN_B>>>();
    scatter_kernel<<<(EE + 255) / 256, 256>>>(rows, cols, vals);

    // SpMM + epilogue
    spmm_kernel<<<(NN + 7) / 8, 256>>>(bias, mask2, prelu_a, out);
}

// round 5
// speedup vs baseline: 2.3628x; 1.1302x over previous
#include <cuda_runtime.h>
#include <cstdint>

#define NN   100000
#define EE   1600000
#define CIN  256
#define COUT 128

#define SCAN_B 1024
#define SCAN_NB ((NN + SCAN_B - 1) / SCAN_B)   // 98

// ---------------- scratch (static device globals; no allocation) ----------------
__device__ float g_feat[(size_t)NN * COUT];   // 51.2 MB
__device__ int   g_count[NN];
__device__ int   g_off[NN + 1];
__device__ int   g_cur[NN];
__device__ int   g_bsum[SCAN_NB];
__device__ int   g_bpre[SCAN_NB];
__device__ int2  g_edge[EE];                  // .x = col, .y = val bits

// ---------------- helpers ----------------
__device__ __forceinline__ uint32_t f2tf32(float f) {
    uint32_t r;
    asm("cvt.rna.tf32.f32 %0, %1;" : "=r"(r) : "f"(f));
    return r;
}

__device__ __forceinline__ void mma_tf32(float* c, const uint32_t* a, uint32_t b0, uint32_t b1) {
    asm volatile(
        "mma.sync.aligned.m16n8k8.row.col.f32.tf32.tf32.f32 "
        "{%0,%1,%2,%3}, {%4,%5,%6,%7}, {%8,%9}, {%0,%1,%2,%3};"
        : "+f"(c[0]), "+f"(c[1]), "+f"(c[2]), "+f"(c[3])
        : "r"(a[0]), "r"(a[1]), "r"(a[2]), "r"(a[3]), "r"(b0), "r"(b1));
}

// ---------------- GEMM: feat = (emb*mask1) @ W^T + b_fc  (tf32 mma.sync) -------
#define KB 32
#define KPAD (KB + 4)

__global__ __launch_bounds__(256) void gemm_mma_kernel(
    const float* __restrict__ emb, const float* __restrict__ mask1,
    const float* __restrict__ W, const float* __restrict__ b_fc)
{
    __shared__ uint32_t as[128][KPAD];   // A tile (tf32 bits), rows x k
    __shared__ uint32_t bs[128][KPAD];   // B tile = W rows (output cols) x k

    const int tid   = threadIdx.x;
    const int wid   = tid >> 5;
    const int lane  = tid & 31;
    const int warpM = wid >> 1;          // 0..3
    const int warpN = wid & 1;           // 0..1
    const int grp   = lane >> 2;         // 0..7
    const int tig   = lane & 3;          // 0..3
    const int row0  = blockIdx.x * 128;

    float acc[2][8][4];
#pragma unroll
    for (int mt = 0; mt < 2; mt++)
#pragma unroll
        for (int nt = 0; nt < 8; nt++)
#pragma unroll
            for (int j = 0; j < 4; j++) acc[mt][nt][j] = 0.f;

    for (int kc = 0; kc < CIN; kc += KB) {
        // --- stage A: (emb*mask1) -> tf32, 128 rows x 32 k ---
#pragma unroll
        for (int i = 0; i < 4; i++) {
            const int idx = i * 256 + tid;       // float4 index, 0..1023
            const int row = idx >> 3;            // 0..127
            const int kq  = (idx & 7) * 4;       // 0..28
            const int grow = row0 + row;
            float4 e = make_float4(0.f, 0.f, 0.f, 0.f);
            if (grow < NN) {
                const float4 a4 = *(const float4*)&emb  [(size_t)grow * CIN + kc + kq];
                const float4 m4 = *(const float4*)&mask1[(size_t)grow * CIN + kc + kq];
                e.x = a4.x * m4.x; e.y = a4.y * m4.y;
                e.z = a4.z * m4.z; e.w = a4.w * m4.w;
            }
            uint4 t;
            t.x = f2tf32(e.x); t.y = f2tf32(e.y); t.z = f2tf32(e.z); t.w = f2tf32(e.w);
            *(uint4*)&as[row][kq] = t;
        }
        // --- stage B: W (COUT x CIN, K-major) -> tf32 ---
#pragma unroll
        for (int i = 0; i < 4; i++) {
            const int idx = i * 256 + tid;
            const int row = idx >> 3;            // output col
            const int kq  = (idx & 7) * 4;
            const float4 w4 = *(const float4*)&W[(size_t)row * CIN + kc + kq];
            uint4 t;
            t.x = f2tf32(w4.x); t.y = f2tf32(w4.y); t.z = f2tf32(w4.z); t.w = f2tf32(w4.w);
            *(uint4*)&bs[row][kq] = t;
        }
        __syncthreads();

        // --- compute: 4 k8-steps ---
#pragma unroll
        for (int ks = 0; ks < 4; ks++) {
            const int k0 = ks * 8;
            uint32_t afr[2][4];
#pragma unroll
            for (int mt = 0; mt < 2; mt++) {
                const int r = warpM * 32 + mt * 16 + grp;
                afr[mt][0] = as[r][k0 + tig];
                afr[mt][1] = as[r + 8][k0 + tig];
                afr[mt][2] = as[r][k0 + tig + 4];
                afr[mt][3] = as[r + 8][k0 + tig + 4];
            }
#pragma unroll
            for (int nt = 0; nt < 8; nt++) {
                const int c = warpN * 64 + nt * 8 + grp;
                const uint32_t b0 = bs[c][k0 + tig];
                const uint32_t b1 = bs[c][k0 + tig + 4];
                mma_tf32(acc[0][nt], afr[0], b0, b1);
                mma_tf32(acc[1][nt], afr[1], b0, b1);
            }
        }
        __syncthreads();
    }

    // --- epilogue: +b_fc, store feat ---
#pragma unroll
    for (int mt = 0; mt < 2; mt++) {
        const int r0 = row0 + warpM * 32 + mt * 16 + grp;
        const int r1 = r0 + 8;
#pragma unroll
        for (int nt = 0; nt < 8; nt++) {
            const int col = warpN * 64 + nt * 8 + 2 * tig;
            const float2 bf = *(const float2*)&b_fc[col];
            if (r0 < NN) {
                float2 o;
                o.x = acc[mt][nt][0] + bf.x;
                o.y = acc[mt][nt][1] + bf.y;
                *(float2*)&g_feat[(size_t)r0 * COUT + col] = o;
            }
            if (r1 < NN) {
                float2 o;
                o.x = acc[mt][nt][2] + bf.x;
                o.y = acc[mt][nt][3] + bf.y;
                *(float2*)&g_feat[(size_t)r1 * COUT + col] = o;
            }
        }
    }
}

// ---------------- CSR construction ----------------
__global__ void zero_counts_kernel() {
    int i = blockIdx.x * blockDim.x + threadIdx.x;
    if (i < NN) g_count[i] = 0;
}

__global__ void hist_kernel(const int* __restrict__ rows) {
    int e = blockIdx.x * blockDim.x + threadIdx.x;
    if (e < EE) atomicAdd(&g_count[rows[e]], 1);
}

__global__ __launch_bounds__(SCAN_B) void scan1_kernel() {
    __shared__ int s[SCAN_B];
    const int t = threadIdx.x;
    const int b = blockIdx.x;
    const int idx = b * SCAN_B + t;
    const int v = (idx < NN) ? g_count[idx] : 0;
    s[t] = v;
    __syncthreads();
#pragma unroll
    for (int off = 1; off < SCAN_B; off <<= 1) {
        int u = 0;
        if (t >= off) u = s[t - off];
        __syncthreads();
        if (t >= off) s[t] += u;
        __syncthreads();
    }
    if (idx < NN) g_off[idx] = s[t] - v;
    if (t == SCAN_B - 1) g_bsum[b] = s[t];
}

__global__ __launch_bounds__(128) void scan2_kernel() {
    __shared__ int s[128];
    const int t = threadIdx.x;
    const int v = (t < SCAN_NB) ? g_bsum[t] : 0;
    s[t] = v;
    __syncthreads();
#pragma unroll
    for (int off = 1; off < 128; off <<= 1) {
        int u = 0;
        if (t >= off) u = s[t - off];
        __syncthreads();
        if (t >= off) s[t] += u;
        __syncthreads();
    }
    if (t < SCAN_NB) g_bpre[t] = s[t] - v;
}

__global__ __launch_bounds__(SCAN_B) void scan3_kernel() {
    const int b = blockIdx.x;
    const int idx = b * SCAN_B + threadIdx.x;
    if (idx < NN) {
        const int o = g_off[idx] + g_bpre[b];
        g_off[idx] = o;
        g_cur[idx] = o;
    }
    if (idx == 0) g_off[NN] = EE;
}

__global__ void scatter_kernel(const int* __restrict__ rows,
                               const int* __restrict__ cols,
                               const float* __restrict__ vals) {
    int e = blockIdx.x * blockDim.x + threadIdx.x;
    if (e < EE) {
        int r = rows[e];
        int p = atomicAdd(&g_cur[r], 1);
        g_edge[p] = make_int2(cols[e], __float_as_int(vals[e]));
    }
}

// ---------------- warp-per-row SpMM + fused epilogue ----------------
__global__ __launch_bounds__(256) void spmm_kernel(
    const float* __restrict__ bias, const float* __restrict__ mask2,
    const float* __restrict__ prelu_a, float* __restrict__ out)
{
    const int warp = blockIdx.x * 8 + (threadIdx.x >> 5);
    if (warp >= NN) return;
    const int lane = threadIdx.x & 31;

    const int start = g_off[warp];
    const int end   = g_off[warp + 1];

    const float4* __restrict__ featv = (const float4*)g_feat;

    float4 acc = make_float4(0.f, 0.f, 0.f, 0.f);

    for (int e0 = start; e0 < end; e0 += 32) {
        const int n = min(32, end - e0);
        int   c = 0;
        float v = 0.f;
        if (lane < n) {
            const int2 ed = g_edge[e0 + lane];
            c = ed.x;
            v = __int_as_float(ed.y);
        }
#pragma unroll 4
        for (int j = 0; j < n; j++) {
            const int   cj = __shfl_sync(0xffffffffu, c, j);
            const float vj = __shfl_sync(0xffffffffu, v, j);
            const float4 f = featv[(size_t)cj * 32 + lane];
            acc.x = fmaf(vj, f.x, acc.x);
            acc.y = fmaf(vj, f.y, acc.y);
            acc.z = fmaf(vj, f.z, acc.z);
            acc.w = fmaf(vj, f.w, acc.w);
        }
    }

    const float4 b = ((const float4*)bias)[lane];
    const float4 m = ((const float4*)mask2)[(size_t)warp * 32 + lane];
    const float  a = prelu_a[0];

    float4 o;
    o.x = (acc.x + b.x) * m.x;
    o.y = (acc.y + b.y) * m.y;
    o.z = (acc.z + b.z) * m.z;
    o.w = (acc.w + b.w) * m.w;
    o.x = o.x > 0.f ? o.x : a * o.x;
    o.y = o.y > 0.f ? o.y : a * o.y;
    o.z = o.z > 0.f ? o.z : a * o.z;
    o.w = o.w > 0.f ? o.w : a * o.w;

    ((float4*)out)[(size_t)warp * 32 + lane] = o;
}

// ---------------- launch (fork-join: CSR build overlaps GEMM) ----------------
static cudaStream_t s_side = nullptr;
static cudaEvent_t  s_evFork = nullptr;
static cudaEvent_t  s_evJoin = nullptr;

extern "C" void kernel_launch(void* const* d_in, const int* in_sizes, int n_in,
                              void* d_out, int out_size)
{
    const float* emb     = (const float*)d_in[0];
    const float* vals    = (const float*)d_in[1];
    const float* W       = (const float*)d_in[2];
    const float* b_fc    = (const float*)d_in[3];
    const float* bias    = (const float*)d_in[4];
    const float* prelu_a = (const float*)d_in[5];
    const float* mask1   = (const float*)d_in[6];
    const float* mask2   = (const float*)d_in[7];
    const int*   rows    = (const int*)d_in[8];
    const int*   cols    = (const int*)d_in[9];
    float*       out     = (float*)d_out;

    if (s_side == nullptr) {   // host-side infra init (first, uncaptured call)
        cudaStreamCreateWithFlags(&s_side, cudaStreamNonBlocking);
        cudaEventCreateWithFlags(&s_evFork, cudaEventDisableTiming);
        cudaEventCreateWithFlags(&s_evJoin, cudaEventDisableTiming);
    }

    // Fork side stream off the (captured) legacy stream
    cudaEventRecord(s_evFork, 0);
    cudaStreamWaitEvent(s_side, s_evFork, 0);

    // Branch A (legacy stream): GEMM via tf32 mma.sync
    gemm_mma_kernel<<<(NN + 127) / 128, 256>>>(emb, mask1, W, b_fc);

    // Branch B (side stream): CSR build
    zero_counts_kernel<<<(NN + 255) / 256, 256, 0, s_side>>>();
    hist_kernel<<<(EE + 255) / 256, 256, 0, s_side>>>(rows);
    scan1_kernel<<<SCAN_NB, SCAN_B, 0, s_side>>>();
    scan2_kernel<<<1, 128, 0, s_side>>>();
    scan3_kernel<<<SCAN_NB, SCAN_B, 0, s_side>>>();
    scatter_kernel<<<(EE + 255) / 256, 256, 0, s_side>>>(rows, cols, vals);

    // Join
    cudaEventRecord(s_evJoin, s_side);
    cudaStreamWaitEvent(0, s_evJoin, 0);

    // SpMM + epilogue (needs both feat and CSR)
    spmm_kernel<<<(NN + 7) / 8, 256>>>(bias, mask2, prelu_a, out);
}

// round 6
// speedup vs baseline: 2.4882x; 1.0531x over previous
#include <cuda_runtime.h>
#include <cuda_fp16.h>
#include <cstdint>

#define NN   100000
#define EE   1600000
#define CIN  256
#define COUT 128

#define SCAN_B 1024
#define SCAN_NB ((NN + SCAN_B - 1) / SCAN_B)   // 98

// ---------------- scratch (static device globals; no allocation) ----------------
__device__ __half g_feat[(size_t)NN * COUT];  // 25.6 MB -> L2-resident
__device__ int   g_count[NN];
__device__ int   g_off[NN + 1];
__device__ int   g_cur[NN];
__device__ int   g_bsum[SCAN_NB];
__device__ int   g_bpre[SCAN_NB];
__device__ int2  g_edge[EE];                  // .x = col, .y = val bits

// ---------------- helpers ----------------
__device__ __forceinline__ uint32_t f2tf32(float f) {
    uint32_t r;
    asm("cvt.rna.tf32.f32 %0, %1;" : "=r"(r) : "f"(f));
    return r;
}

__device__ __forceinline__ void mma_tf32(float* c, const uint32_t* a, uint32_t b0, uint32_t b1) {
    asm volatile(
        "mma.sync.aligned.m16n8k8.row.col.f32.tf32.tf32.f32 "
        "{%0,%1,%2,%3}, {%4,%5,%6,%7}, {%8,%9}, {%0,%1,%2,%3};"
        : "+f"(c[0]), "+f"(c[1]), "+f"(c[2]), "+f"(c[3])
        : "r"(a[0]), "r"(a[1]), "r"(a[2]), "r"(a[3]), "r"(b0), "r"(b1));
}

// ---------------- GEMM: feat = (emb*mask1) @ W^T + b_fc  (tf32 mma.sync) -------
#define KB 32
#define KPAD (KB + 4)

__global__ __launch_bounds__(256) void gemm_mma_kernel(
    const float* __restrict__ emb, const float* __restrict__ mask1,
    const float* __restrict__ W, const float* __restrict__ b_fc)
{
    __shared__ uint32_t as[128][KPAD];   // A tile (tf32 bits), rows x k
    __shared__ uint32_t bs[128][KPAD];   // B tile = W rows (output cols) x k

    const int tid   = threadIdx.x;
    const int wid   = tid >> 5;
    const int lane  = tid & 31;
    const int warpM = wid >> 1;          // 0..3
    const int warpN = wid & 1;           // 0..1
    const int grp   = lane >> 2;         // 0..7
    const int tig   = lane & 3;          // 0..3
    const int row0  = blockIdx.x * 128;

    float acc[2][8][4];
#pragma unroll
    for (int mt = 0; mt < 2; mt++)
#pragma unroll
        for (int nt = 0; nt < 8; nt++)
#pragma unroll
            for (int j = 0; j < 4; j++) acc[mt][nt][j] = 0.f;

    for (int kc = 0; kc < CIN; kc += KB) {
        // --- stage A: (emb*mask1) -> tf32, 128 rows x 32 k ---
#pragma unroll
        for (int i = 0; i < 4; i++) {
            const int idx = i * 256 + tid;       // float4 index, 0..1023
            const int row = idx >> 3;            // 0..127
            const int kq  = (idx & 7) * 4;       // 0..28
            const int grow = row0 + row;
            float4 e = make_float4(0.f, 0.f, 0.f, 0.f);
            if (grow < NN) {
                const float4 a4 = *(const float4*)&emb  [(size_t)grow * CIN + kc + kq];
                const float4 m4 = *(const float4*)&mask1[(size_t)grow * CIN + kc + kq];
                e.x = a4.x * m4.x; e.y = a4.y * m4.y;
                e.z = a4.z * m4.z; e.w = a4.w * m4.w;
            }
            uint4 t;
            t.x = f2tf32(e.x); t.y = f2tf32(e.y); t.z = f2tf32(e.z); t.w = f2tf32(e.w);
            *(uint4*)&as[row][kq] = t;
        }
        // --- stage B: W (COUT x CIN, K-major) -> tf32 ---
#pragma unroll
        for (int i = 0; i < 4; i++) {
            const int idx = i * 256 + tid;
            const int row = idx >> 3;            // output col
            const int kq  = (idx & 7) * 4;
            const float4 w4 = *(const float4*)&W[(size_t)row * CIN + kc + kq];
            uint4 t;
            t.x = f2tf32(w4.x); t.y = f2tf32(w4.y); t.z = f2tf32(w4.z); t.w = f2tf32(w4.w);
            *(uint4*)&bs[row][kq] = t;
        }
        __syncthreads();

        // --- compute: 4 k8-steps ---
#pragma unroll
        for (int ks = 0; ks < 4; ks++) {
            const int k0 = ks * 8;
            uint32_t afr[2][4];
#pragma unroll
            for (int mt = 0; mt < 2; mt++) {
                const int r = warpM * 32 + mt * 16 + grp;
                afr[mt][0] = as[r][k0 + tig];
                afr[mt][1] = as[r + 8][k0 + tig];
                afr[mt][2] = as[r][k0 + tig + 4];
                afr[mt][3] = as[r + 8][k0 + tig + 4];
            }
#pragma unroll
            for (int nt = 0; nt < 8; nt++) {
                const int c = warpN * 64 + nt * 8 + grp;
                const uint32_t b0 = bs[c][k0 + tig];
                const uint32_t b1 = bs[c][k0 + tig + 4];
                mma_tf32(acc[0][nt], afr[0], b0, b1);
                mma_tf32(acc[1][nt], afr[1], b0, b1);
            }
        }
        __syncthreads();
    }

    // --- epilogue: +b_fc, convert to fp16, store feat ---
#pragma unroll
    for (int mt = 0; mt < 2; mt++) {
        const int r0 = row0 + warpM * 32 + mt * 16 + grp;
        const int r1 = r0 + 8;
#pragma unroll
        for (int nt = 0; nt < 8; nt++) {
            const int col = warpN * 64 + nt * 8 + 2 * tig;
            const float2 bf = *(const float2*)&b_fc[col];
            if (r0 < NN) {
                const __half2 h = __float22half2_rn(
                    make_float2(acc[mt][nt][0] + bf.x, acc[mt][nt][1] + bf.y));
                *(__half2*)&g_feat[(size_t)r0 * COUT + col] = h;
            }
            if (r1 < NN) {
                const __half2 h = __float22half2_rn(
                    make_float2(acc[mt][nt][2] + bf.x, acc[mt][nt][3] + bf.y));
                *(__half2*)&g_feat[(size_t)r1 * COUT + col] = h;
            }
        }
    }
}

// ---------------- CSR construction ----------------
__global__ void zero_counts_kernel() {
    int i = blockIdx.x * blockDim.x + threadIdx.x;
    if (i < NN) g_count[i] = 0;
}

__global__ void hist_kernel(const int* __restrict__ rows) {
    int e = blockIdx.x * blockDim.x + threadIdx.x;
    if (e < EE) atomicAdd(&g_count[rows[e]], 1);
}

__global__ __launch_bounds__(SCAN_B) void scan1_kernel() {
    __shared__ int s[SCAN_B];
    const int t = threadIdx.x;
    const int b = blockIdx.x;
    const int idx = b * SCAN_B + t;
    const int v = (idx < NN) ? g_count[idx] : 0;
    s[t] = v;
    __syncthreads();
#pragma unroll
    for (int off = 1; off < SCAN_B; off <<= 1) {
        int u = 0;
        if (t >= off) u = s[t - off];
        __syncthreads();
        if (t >= off) s[t] += u;
        __syncthreads();
    }
    if (idx < NN) g_off[idx] = s[t] - v;
    if (t == SCAN_B - 1) g_bsum[b] = s[t];
}

__global__ __launch_bounds__(128) void scan2_kernel() {
    __shared__ int s[128];
    const int t = threadIdx.x;
    const int v = (t < SCAN_NB) ? g_bsum[t] : 0;
    s[t] = v;
    __syncthreads();
#pragma unroll
    for (int off = 1; off < 128; off <<= 1) {
        int u = 0;
        if (t >= off) u = s[t - off];
        __syncthreads();
        if (t >= off) s[t] += u;
        __syncthreads();
    }
    if (t < SCAN_NB) g_bpre[t] = s[t] - v;
}

__global__ __launch_bounds__(SCAN_B) void scan3_kernel() {
    const int b = blockIdx.x;
    const int idx = b * SCAN_B + threadIdx.x;
    if (idx < NN) {
        const int o = g_off[idx] + g_bpre[b];
        g_off[idx] = o;
        g_cur[idx] = o;
    }
    if (idx == 0) g_off[NN] = EE;
}

__global__ void scatter_kernel(const int* __restrict__ rows,
                               const int* __restrict__ cols,
                               const float* __restrict__ vals) {
    int e = blockIdx.x * blockDim.x + threadIdx.x;
    if (e < EE) {
        int r = rows[e];
        int p = atomicAdd(&g_cur[r], 1);
        g_edge[p] = make_int2(cols[e], __float_as_int(vals[e]));
    }
}

// ---------------- warp-per-row SpMM (fp16 gather) + fused epilogue ----------------
__global__ __launch_bounds__(256) void spmm_kernel(
    const float* __restrict__ bias, const float* __restrict__ mask2,
    const float* __restrict__ prelu_a, float* __restrict__ out)
{
    const int warp = blockIdx.x * 8 + (threadIdx.x >> 5);
    if (warp >= NN) return;
    const int lane = threadIdx.x & 31;

    const int start = g_off[warp];
    const int end   = g_off[warp + 1];

    float4 acc = make_float4(0.f, 0.f, 0.f, 0.f);

    for (int e0 = start; e0 < end; e0 += 32) {
        const int n = min(32, end - e0);
        int   c = 0;
        float v = 0.f;
        if (lane < n) {
            const int2 ed = g_edge[e0 + lane];
            c = ed.x;
            v = __int_as_float(ed.y);
        }
#pragma unroll 4
        for (int j = 0; j < n; j++) {
            const int   cj = __shfl_sync(0xffffffffu, c, j);
            const float vj = __shfl_sync(0xffffffffu, v, j);
            // lane owns cols [4*lane, 4*lane+3]: 4 halfs = 8 bytes
            const uint2 hv = *(const uint2*)&g_feat[(size_t)cj * COUT + lane * 4];
            const float2 f0 = __half22float2(*(const __half2*)&hv.x);
            const float2 f1 = __half22float2(*(const __half2*)&hv.y);
            acc.x = fmaf(vj, f0.x, acc.x);
            acc.y = fmaf(vj, f0.y, acc.y);
            acc.z = fmaf(vj, f1.x, acc.z);
            acc.w = fmaf(vj, f1.y, acc.w);
        }
    }

    const float4 b = ((const float4*)bias)[lane];
    const float4 m = ((const float4*)mask2)[(size_t)warp * 32 + lane];
    const float  a = prelu_a[0];

    float4 o;
    o.x = (acc.x + b.x) * m.x;
    o.y = (acc.y + b.y) * m.y;
    o.z = (acc.z + b.z) * m.z;
    o.w = (acc.w + b.w) * m.w;
    o.x = o.x > 0.f ? o.x : a * o.x;
    o.y = o.y > 0.f ? o.y : a * o.y;
    o.z = o.z > 0.f ? o.z : a * o.z;
    o.w = o.w > 0.f ? o.w : a * o.w;

    ((float4*)out)[(size_t)warp * 32 + lane] = o;
}

// ---------------- launch (fork-join: CSR build overlaps GEMM) ----------------
static cudaStream_t s_side = nullptr;
static cudaEvent_t  s_evFork = nullptr;
static cudaEvent_t  s_evJoin = nullptr;

extern "C" void kernel_launch(void* const* d_in, const int* in_sizes, int n_in,
                              void* d_out, int out_size)
{
    const float* emb     = (const float*)d_in[0];
    const float* vals    = (const float*)d_in[1];
    const float* W       = (const float*)d_in[2];
    const float* b_fc    = (const float*)d_in[3];
    const float* bias    = (const float*)d_in[4];
    const float* prelu_a = (const float*)d_in[5];
    const float* mask1   = (const float*)d_in[6];
    const float* mask2   = (const float*)d_in[7];
    const int*   rows    = (const int*)d_in[8];
    const int*   cols    = (const int*)d_in[9];
    float*       out     = (float*)d_out;

    if (s_side == nullptr) {   // host-side infra init (first, uncaptured call)
        cudaStreamCreateWithFlags(&s_side, cudaStreamNonBlocking);
        cudaEventCreateWithFlags(&s_evFork, cudaEventDisableTiming);
        cudaEventCreateWithFlags(&s_evJoin, cudaEventDisableTiming);
    }

    // Fork side stream off the (captured) legacy stream
    cudaEventRecord(s_evFork, 0);
    cudaStreamWaitEvent(s_side, s_evFork, 0);

    // Branch A (legacy stream): GEMM via tf32 mma.sync
    gemm_mma_kernel<<<(NN + 127) / 128, 256>>>(emb, mask1, W, b_fc);

    // Branch B (side stream): CSR build
    zero_counts_kernel<<<(NN + 255) / 256, 256, 0, s_side>>>();
    hist_kernel<<<(EE + 255) / 256, 256, 0, s_side>>>(rows);
    scan1_kernel<<<SCAN_NB, SCAN_B, 0, s_side>>>();
    scan2_kernel<<<1, 128, 0, s_side>>>();
    scan3_kernel<<<SCAN_NB, SCAN_B, 0, s_side>>>();
    scatter_kernel<<<(EE + 255) / 256, 256, 0, s_side>>>(rows, cols, vals);

    // Join
    cudaEventRecord(s_evJoin, s_side);
    cudaStreamWaitEvent(0, s_evJoin, 0);

    // SpMM + epilogue (needs both feat and CSR)
    spmm_kernel<<<(NN + 7) / 8, 256>>>(bias, mask2, prelu_a, out);
}